// round 13
// baseline (speedup 1.0000x reference)
#include <cuda_runtime.h>
#include <cstdint>

// AttentionLayer: B=2048, N=64, D=256, H=16
//   m_i[h]  = sum_d members[b,i,d]*item[b,d]*W1[d,h]
//   s[h]    = sum_i m_i[h] ; pre = 64*m_i - s + b1 ; relu ; logit = relu@W2 + b2
//   out[b,i] = softmax_i(logit)
//
// R13: R6 lane mapping (4 heads x 16 d -> 4 LDS.128 per row, HALF the LDS
// wavefronts of R8/R12) + R12 shared TMA ring (cp.async.bulk + full/empty
// mbarriers, single fill, no LDGSTS, no block barriers in main loop).
// Block = 64 thr = 2 warps = 1 batch; warp p owns heads 8p..8p+7; lane owns
// heads h0=8p+4*(lane&1)..+3 x d-quads (16t + (lane>>1)).

constexpr int Bb = 2048;
constexpr int Nn = 64;
constexpr int Dd = 256;
constexpr int Hh = 16;
constexpr int THREADS = 64;
constexpr int NSLOT = 4;               // ring slots
constexpr int SROWS = 4;               // rows per slot (4 KB)
constexpr int ITERS = Nn / SROWS;      // 16
constexpr int MSTR = 18;               // mS row stride (72 B, 8B-aligned)

typedef unsigned long long ull;

#define FMA2(acc, a, w)  asm("fma.rn.f32x2 %0, %1, %2, %0;" : "+l"(acc) : "l"(a), "l"(w))
#define ADD2(d, a, b_)   asm("add.rn.f32x2 %0, %1, %2;" : "=l"(d) : "l"(a), "l"(b_))
#define PACK2(d, lo, hi) asm("mov.b64 %0, {%1, %2};" : "=l"(d) : "f"(lo), "f"(hi))
#define UNPACK2(lo, hi, v) asm("mov.b64 {%0, %1}, %2;" : "=f"(lo), "=f"(hi) : "l"(v))

__device__ __forceinline__ uint32_t smem_u32(const void* p) {
    uint32_t a;
    asm("{ .reg .u64 t; cvta.to.shared.u64 t, %1; cvt.u32.u64 %0, t; }"
        : "=r"(a) : "l"(p));
    return a;
}
__device__ __forceinline__ void mbar_init(uint32_t addr, uint32_t count) {
    asm volatile("mbarrier.init.shared.b64 [%0], %1;" :: "r"(addr), "r"(count) : "memory");
}
__device__ __forceinline__ void mbar_arrive(uint32_t addr) {
    asm volatile("mbarrier.arrive.shared.b64 _, [%0];" :: "r"(addr) : "memory");
}
__device__ __forceinline__ void mbar_expect_tx(uint32_t addr, uint32_t bytes) {
    asm volatile("mbarrier.arrive.expect_tx.shared.b64 _, [%0], %1;"
                 :: "r"(addr), "r"(bytes) : "memory");
}
__device__ __forceinline__ void mbar_wait(uint32_t addr, uint32_t phase) {
    asm volatile(
        "{\n\t.reg .pred P;\n\t"
        "W%=:\n\t"
        "mbarrier.try_wait.parity.acquire.cta.shared::cta.b64 P, [%0], %1, 0x989680;\n\t"
        "@P bra D%=;\n\t"
        "bra W%=;\n\t"
        "D%=:\n\t}"
        :: "r"(addr), "r"(phase) : "memory");
}
__device__ __forceinline__ void tma_bulk_1d(uint32_t dst, const void* src,
                                            uint32_t bytes, uint32_t mbar) {
    asm volatile(
        "cp.async.bulk.shared::cta.global.mbarrier::complete_tx::bytes [%0], [%1], %2, [%3];"
        :: "r"(dst), "l"(src), "r"(bytes), "r"(mbar) : "memory");
}

__global__ __launch_bounds__(THREADS, 8)
void attn_kernel(const float* __restrict__ members,
                 const float* __restrict__ item,
                 const float* __restrict__ W1,
                 const float* __restrict__ b1,
                 const float* __restrict__ W2,
                 const float* __restrict__ b2,
                 float* __restrict__ out)
{
    __shared__ __align__(16) float4 ringS[NSLOT][SROWS][Dd / 4];  // 16 KB shared ring
    __shared__ float  mS[Nn * MSTR];       // 4.6 KB (lanes write disjoint head spans)
    __shared__ float  sS[Hh];
    __shared__ float  red[2][2];           // [max|sum][warp]
    __shared__ __align__(8) ull mbar[2 * NSLOT];   // full[0..3], empty[4..7]

    const int tid  = threadIdx.x;
    const int p    = tid >> 5;             // warp: heads 8p..8p+7
    const int lane = tid & 31;
    const int hgrp = lane & 1;             // 0: heads 8p..+3, 1: heads 8p+4..+7
    const int ds   = lane >> 1;            // d-sixteenth: quads 16t + ds
    const int h0   = 8 * p + 4 * hgrp;     // lane's first head (mult of 4)
    const int b    = blockIdx.x;

    const float* growF = members + (size_t)b * Nn * Dd;
    const uint32_t ringBase = smem_u32(&ringS[0][0][0]);
    const uint32_t mbarBase = smem_u32(&mbar[0]);
    #define FULL(s)  (mbarBase + (s) * 8)
    #define EMPTY(s) (mbarBase + (NSLOT + (s)) * 8)

    // ---- mbarrier init + prologue fills ----
    if (tid == 0) {
        #pragma unroll
        for (int s = 0; s < NSLOT; s++) {
            mbar_init(FULL(s), 1);         // 1 arrival: the expect_tx
            mbar_init(EMPTY(s), 2);        // 1 arrival per warp
        }
    }
    asm volatile("fence.proxy.async.shared::cta;" ::: "memory");
    __syncthreads();
    if (tid == 0) {
        #pragma unroll
        for (int s = 0; s < NSLOT; s++) {
            mbar_expect_tx(FULL(s), SROWS * Dd * 4);
            tma_bulk_1d(ringBase + s * 4096, growF + s * SROWS * Dd,
                        SROWS * Dd * 4, FULL(s));
        }
    }

    // ---- register weights: lane's 4 heads x 16 d ----
    // wreg[8t + j]   = (W1[d0  ][h0+j]*it[d0  ], W1[d0+1][h0+j]*it[d0+1])
    // wreg[8t + 4+j] = (W1[d0+2][h0+j]*it[d0+2], W1[d0+3][h0+j]*it[d0+3])
    // for quad d0 = (16t + ds)*4, t = 0..3, j = 0..3
    const float* itG = item + (size_t)b * Dd;
    ull wreg[32];
    #pragma unroll
    for (int t = 0; t < 4; t++) {
        const int d0 = (16 * t + ds) * 4;
        const float4 it4 = __ldg((const float4*)&itG[d0]);
        const float4 wa = __ldg((const float4*)&W1[(d0 + 0) * Hh + h0]);
        const float4 wb = __ldg((const float4*)&W1[(d0 + 1) * Hh + h0]);
        const float4 wc = __ldg((const float4*)&W1[(d0 + 2) * Hh + h0]);
        const float4 wd = __ldg((const float4*)&W1[(d0 + 3) * Hh + h0]);
        PACK2(wreg[8 * t + 0], wa.x * it4.x, wb.x * it4.y);
        PACK2(wreg[8 * t + 1], wa.y * it4.x, wb.y * it4.y);
        PACK2(wreg[8 * t + 2], wa.z * it4.x, wb.z * it4.y);
        PACK2(wreg[8 * t + 3], wa.w * it4.x, wb.w * it4.y);
        PACK2(wreg[8 * t + 4], wc.x * it4.z, wd.x * it4.w);
        PACK2(wreg[8 * t + 5], wc.y * it4.z, wd.y * it4.w);
        PACK2(wreg[8 * t + 6], wc.z * it4.z, wd.z * it4.w);
        PACK2(wreg[8 * t + 7], wc.w * it4.z, wd.w * it4.w);
    }

    // ---- main loop: 16 iterations x 4 rows ----
    ull sA0 = 0ull, sA1 = 0ull;            // (s_h0,s_h1),(s_h2,s_h3) post-reduce
    for (int i = 0; i < ITERS; i++) {
        const int s  = i & (NSLOT - 1);
        const uint32_t ph = (i >> 2) & 1;  // slot reuse parity
        mbar_wait(FULL(s), ph);            // TMA delivered slot s (acquire)

        ull mm[4][2];                      // [row][(h0,h1)|(h2,h3)]
        #pragma unroll
        for (int rr = 0; rr < SROWS; rr++) {
            const ulonglong2* rp = (const ulonglong2*)&ringS[s][rr][0];
            ull a0 = 0ull, a1 = 0ull, a2 = 0ull, a3 = 0ull;
            #pragma unroll
            for (int t = 0; t < 4; t++) {
                const ulonglong2 u = rp[16 * t + ds];  // 4 LDS.128/row, 2-way bcast
                FMA2(a0, u.x, wreg[8 * t + 0]);
                FMA2(a1, u.x, wreg[8 * t + 1]);
                FMA2(a2, u.x, wreg[8 * t + 2]);
                FMA2(a3, u.x, wreg[8 * t + 3]);
                FMA2(a0, u.y, wreg[8 * t + 4]);
                FMA2(a1, u.y, wreg[8 * t + 5]);
                FMA2(a2, u.y, wreg[8 * t + 6]);
                FMA2(a3, u.y, wreg[8 * t + 7]);
            }
            float x, y, m0, m1, m2, m3;
            UNPACK2(x, y, a0); m0 = x + y;
            UNPACK2(x, y, a1); m1 = x + y;
            UNPACK2(x, y, a2); m2 = x + y;
            UNPACK2(x, y, a3); m3 = x + y;
            PACK2(mm[rr][0], m0, m1);
            PACK2(mm[rr][1], m2, m3);
        }

        // 8 independent 4-level butterflies over the 16 ds lanes (xor 2,4,8,16)
        ull tmp;
        #pragma unroll
        for (int o = 2; o <= 16; o <<= 1) {
            #pragma unroll
            for (int rr = 0; rr < SROWS; rr++) {
                tmp = __shfl_xor_sync(0xffffffffu, mm[rr][0], o); ADD2(mm[rr][0], mm[rr][0], tmp);
                tmp = __shfl_xor_sync(0xffffffffu, mm[rr][1], o); ADD2(mm[rr][1], mm[rr][1], tmp);
            }
        }
        #pragma unroll
        for (int rr = 0; rr < SROWS; rr++) {
            ADD2(sA0, sA0, mm[rr][0]);
            ADD2(sA1, sA1, mm[rr][1]);
        }

        if (lane < 2) {             // ds==0 lanes publish their 4 heads x 4 rows
            #pragma unroll
            for (int rr = 0; rr < SROWS; rr++) {
                *(ull*)&mS[(SROWS * i + rr) * MSTR + h0]     = mm[rr][0];
                *(ull*)&mS[(SROWS * i + rr) * MSTR + h0 + 2] = mm[rr][1];
            }
        }

        __syncwarp();               // whole warp done reading slot s
        if (lane == 0) mbar_arrive(EMPTY(s));
        if (tid == 0 && i + NSLOT < ITERS) {
            mbar_wait(EMPTY(s), ph);               // both warps released slot s
            mbar_expect_tx(FULL(s), SROWS * Dd * 4);
            tma_bulk_1d(ringBase + s * 4096, growF + (i + NSLOT) * SROWS * Dd,
                        SROWS * Dd * 4, FULL(s));
        }
    }

    // s fully reduced across lanes; lanes 0,1 publish 4 heads each
    if (lane < 2) {
        *(ull*)&sS[h0]     = sA0;
        *(ull*)&sS[h0 + 2] = sA1;
    }
    __syncthreads();                // barrier #1: mS + sS complete

    // ---- epilogue: row = tid ----
    const int row = tid;
    float logit = __ldg(b2);
    #pragma unroll
    for (int hh = 0; hh < 16; hh++) {
        const float pre = 64.f * mS[row * MSTR + hh] + __ldg(&b1[hh]) - sS[hh];
        logit += fmaxf(pre, 0.f) * __ldg(&W2[hh]);
    }

    float mx = logit;
    #pragma unroll
    for (int o = 16; o >= 1; o >>= 1)
        mx = fmaxf(mx, __shfl_xor_sync(0xffffffffu, mx, o));
    if (lane == 0) red[0][p] = mx;
    __syncthreads();                // barrier #2
    const float mxAll = fmaxf(red[0][0], red[0][1]);

    const float e = __expf(logit - mxAll);
    float sm = e;
    #pragma unroll
    for (int o = 16; o >= 1; o >>= 1)
        sm += __shfl_xor_sync(0xffffffffu, sm, o);
    if (lane == 0) red[1][p] = sm;
    __syncthreads();                // barrier #3
    const float inv = 1.0f / (red[1][0] + red[1][1]);

    out[(size_t)b * Nn + row] = e * inv;
}

extern "C" void kernel_launch(void* const* d_in, const int* in_sizes, int n_in,
                              void* d_out, int out_size)
{
    attn_kernel<<<Bb, THREADS>>>(
        (const float*)d_in[0],   // members_embeds [2048,64,256]
        (const float*)d_in[1],   // item_embeds    [2048,256]
        (const float*)d_in[2],   // W1 [256,16]
        (const float*)d_in[3],   // b1 [16]
        (const float*)d_in[4],   // W2 [16,1]
        (const float*)d_in[5],   // b2 [1]
        (float*)d_out);          // out [2048,64]
}

// round 14
// speedup vs baseline: 1.6618x; 1.6618x over previous
#include <cuda_runtime.h>
#include <cstdint>

// AttentionLayer: B=2048, N=64, D=256, H=16
//   m_i[h]  = sum_d members[b,i,d]*item[b,d]*W1[d,h]
//   s[h]    = sum_i m_i[h] ; pre = 64*m_i - s + b1 ; relu ; logit = relu@W2 + b2
//   out[b,i] = softmax_i(logit)
//
// R14 (= R13 with SROWS=2 to kill the register spill): 4-heads x 16-d lane
// mapping (4 LDS.128 per row = half of R8's crossbar traffic) + shared TMA
// ring (cp.async.bulk + full/empty mbarriers, single fill, no LDGSTS, no
// block barriers in main loop). Block = 64 thr = 2 warps = 1 batch; warp p
// owns heads 8p..8p+7; lane owns heads h0=8p+4*(lane&1)..+3 x quads
// (16t + (lane>>1)). 2 rows/iter -> mm[2][2] temporaries, ~105 regs.

constexpr int Bb = 2048;
constexpr int Nn = 64;
constexpr int Dd = 256;
constexpr int Hh = 16;
constexpr int THREADS = 64;
constexpr int NSLOT = 4;               // ring slots
constexpr int SROWS = 2;               // rows per slot (2 KB)
constexpr int ITERS = Nn / SROWS;      // 32
constexpr int MSTR = 18;               // mS row stride (72 B, 8B-aligned)

typedef unsigned long long ull;

#define FMA2(acc, a, w)  asm("fma.rn.f32x2 %0, %1, %2, %0;" : "+l"(acc) : "l"(a), "l"(w))
#define ADD2(d, a, b_)   asm("add.rn.f32x2 %0, %1, %2;" : "=l"(d) : "l"(a), "l"(b_))
#define PACK2(d, lo, hi) asm("mov.b64 %0, {%1, %2};" : "=l"(d) : "f"(lo), "f"(hi))
#define UNPACK2(lo, hi, v) asm("mov.b64 {%0, %1}, %2;" : "=f"(lo), "=f"(hi) : "l"(v))

__device__ __forceinline__ uint32_t smem_u32(const void* p) {
    uint32_t a;
    asm("{ .reg .u64 t; cvta.to.shared.u64 t, %1; cvt.u32.u64 %0, t; }"
        : "=r"(a) : "l"(p));
    return a;
}
__device__ __forceinline__ void mbar_init(uint32_t addr, uint32_t count) {
    asm volatile("mbarrier.init.shared.b64 [%0], %1;" :: "r"(addr), "r"(count) : "memory");
}
__device__ __forceinline__ void mbar_arrive(uint32_t addr) {
    asm volatile("mbarrier.arrive.shared.b64 _, [%0];" :: "r"(addr) : "memory");
}
__device__ __forceinline__ void mbar_expect_tx(uint32_t addr, uint32_t bytes) {
    asm volatile("mbarrier.arrive.expect_tx.shared.b64 _, [%0], %1;"
                 :: "r"(addr), "r"(bytes) : "memory");
}
__device__ __forceinline__ void mbar_wait(uint32_t addr, uint32_t phase) {
    asm volatile(
        "{\n\t.reg .pred P;\n\t"
        "W%=:\n\t"
        "mbarrier.try_wait.parity.acquire.cta.shared::cta.b64 P, [%0], %1, 0x989680;\n\t"
        "@P bra D%=;\n\t"
        "bra W%=;\n\t"
        "D%=:\n\t}"
        :: "r"(addr), "r"(phase) : "memory");
}
__device__ __forceinline__ void tma_bulk_1d(uint32_t dst, const void* src,
                                            uint32_t bytes, uint32_t mbar) {
    asm volatile(
        "cp.async.bulk.shared::cta.global.mbarrier::complete_tx::bytes [%0], [%1], %2, [%3];"
        :: "r"(dst), "l"(src), "r"(bytes), "r"(mbar) : "memory");
}

__global__ __launch_bounds__(THREADS, 8)
void attn_kernel(const float* __restrict__ members,
                 const float* __restrict__ item,
                 const float* __restrict__ W1,
                 const float* __restrict__ b1,
                 const float* __restrict__ W2,
                 const float* __restrict__ b2,
                 float* __restrict__ out)
{
    __shared__ __align__(16) float4 ringS[NSLOT][SROWS][Dd / 4];  // 8 KB shared ring
    __shared__ float  mS[Nn * MSTR];       // 4.6 KB (lanes write disjoint head spans)
    __shared__ float  sS[Hh];
    __shared__ float  red[2][2];           // [max|sum][warp]
    __shared__ __align__(8) ull mbar[2 * NSLOT];   // full[0..3], empty[4..7]

    const int tid  = threadIdx.x;
    const int p    = tid >> 5;             // warp: heads 8p..8p+7
    const int lane = tid & 31;
    const int hgrp = lane & 1;             // 0: heads 8p..+3, 1: heads 8p+4..+7
    const int ds   = lane >> 1;            // d-sixteenth: quads 16t + ds
    const int h0   = 8 * p + 4 * hgrp;     // lane's first head (mult of 4)
    const int b    = blockIdx.x;

    const float* growF = members + (size_t)b * Nn * Dd;
    const uint32_t ringBase = smem_u32(&ringS[0][0][0]);
    const uint32_t mbarBase = smem_u32(&mbar[0]);
    #define FULL(s)  (mbarBase + (s) * 8)
    #define EMPTY(s) (mbarBase + (NSLOT + (s)) * 8)

    // ---- mbarrier init + prologue fills ----
    if (tid == 0) {
        #pragma unroll
        for (int s = 0; s < NSLOT; s++) {
            mbar_init(FULL(s), 1);         // 1 arrival: the expect_tx
            mbar_init(EMPTY(s), 2);        // 1 arrival per warp
        }
    }
    asm volatile("fence.proxy.async.shared::cta;" ::: "memory");
    __syncthreads();
    if (tid == 0) {
        #pragma unroll
        for (int s = 0; s < NSLOT; s++) {
            mbar_expect_tx(FULL(s), SROWS * Dd * 4);
            tma_bulk_1d(ringBase + s * (SROWS * Dd * 4), growF + s * SROWS * Dd,
                        SROWS * Dd * 4, FULL(s));
        }
    }

    // ---- register weights: lane's 4 heads x 16 d ----
    // wreg[8t + j]   = (W1[d0  ][h0+j]*it[d0  ], W1[d0+1][h0+j]*it[d0+1])
    // wreg[8t + 4+j] = (W1[d0+2][h0+j]*it[d0+2], W1[d0+3][h0+j]*it[d0+3])
    // for quad d0 = (16t + ds)*4, t = 0..3, j = 0..3
    const float* itG = item + (size_t)b * Dd;
    ull wreg[32];
    #pragma unroll
    for (int t = 0; t < 4; t++) {
        const int d0 = (16 * t + ds) * 4;
        const float4 it4 = __ldg((const float4*)&itG[d0]);
        const float4 wa = __ldg((const float4*)&W1[(d0 + 0) * Hh + h0]);
        const float4 wb = __ldg((const float4*)&W1[(d0 + 1) * Hh + h0]);
        const float4 wc = __ldg((const float4*)&W1[(d0 + 2) * Hh + h0]);
        const float4 wd = __ldg((const float4*)&W1[(d0 + 3) * Hh + h0]);
        PACK2(wreg[8 * t + 0], wa.x * it4.x, wb.x * it4.y);
        PACK2(wreg[8 * t + 1], wa.y * it4.x, wb.y * it4.y);
        PACK2(wreg[8 * t + 2], wa.z * it4.x, wb.z * it4.y);
        PACK2(wreg[8 * t + 3], wa.w * it4.x, wb.w * it4.y);
        PACK2(wreg[8 * t + 4], wc.x * it4.z, wd.x * it4.w);
        PACK2(wreg[8 * t + 5], wc.y * it4.z, wd.y * it4.w);
        PACK2(wreg[8 * t + 6], wc.z * it4.z, wd.z * it4.w);
        PACK2(wreg[8 * t + 7], wc.w * it4.z, wd.w * it4.w);
    }

    // ---- main loop: 32 iterations x 2 rows ----
    ull sA0 = 0ull, sA1 = 0ull;            // (s_h0,s_h1),(s_h2,s_h3) post-reduce
    for (int i = 0; i < ITERS; i++) {
        const int s  = i & (NSLOT - 1);
        const uint32_t ph = (i >> 2) & 1;  // slot reuse parity
        mbar_wait(FULL(s), ph);            // TMA delivered slot s (acquire)

        ull mm[SROWS][2];                  // [row][(h0,h1)|(h2,h3)]
        #pragma unroll
        for (int rr = 0; rr < SROWS; rr++) {
            const ulonglong2* rp = (const ulonglong2*)&ringS[s][rr][0];
            ull a0 = 0ull, a1 = 0ull, a2 = 0ull, a3 = 0ull;
            #pragma unroll
            for (int t = 0; t < 4; t++) {
                const ulonglong2 u = rp[16 * t + ds];  // 4 LDS.128/row, 2-way bcast
                FMA2(a0, u.x, wreg[8 * t + 0]);
                FMA2(a1, u.x, wreg[8 * t + 1]);
                FMA2(a2, u.x, wreg[8 * t + 2]);
                FMA2(a3, u.x, wreg[8 * t + 3]);
                FMA2(a0, u.y, wreg[8 * t + 4]);
                FMA2(a1, u.y, wreg[8 * t + 5]);
                FMA2(a2, u.y, wreg[8 * t + 6]);
                FMA2(a3, u.y, wreg[8 * t + 7]);
            }
            float x, y, m0, m1, m2, m3;
            UNPACK2(x, y, a0); m0 = x + y;
            UNPACK2(x, y, a1); m1 = x + y;
            UNPACK2(x, y, a2); m2 = x + y;
            UNPACK2(x, y, a3); m3 = x + y;
            PACK2(mm[rr][0], m0, m1);
            PACK2(mm[rr][1], m2, m3);
        }

        // 4 independent 4-level butterflies over the 16 ds lanes (xor 2,4,8,16)
        ull tmp;
        #pragma unroll
        for (int o = 2; o <= 16; o <<= 1) {
            tmp = __shfl_xor_sync(0xffffffffu, mm[0][0], o); ADD2(mm[0][0], mm[0][0], tmp);
            tmp = __shfl_xor_sync(0xffffffffu, mm[0][1], o); ADD2(mm[0][1], mm[0][1], tmp);
            tmp = __shfl_xor_sync(0xffffffffu, mm[1][0], o); ADD2(mm[1][0], mm[1][0], tmp);
            tmp = __shfl_xor_sync(0xffffffffu, mm[1][1], o); ADD2(mm[1][1], mm[1][1], tmp);
        }
        ADD2(sA0, sA0, mm[0][0]);  ADD2(sA0, sA0, mm[1][0]);
        ADD2(sA1, sA1, mm[0][1]);  ADD2(sA1, sA1, mm[1][1]);

        if (lane < 2) {             // ds==0 lanes publish their 4 heads x 2 rows
            #pragma unroll
            for (int rr = 0; rr < SROWS; rr++) {
                *(ull*)&mS[(SROWS * i + rr) * MSTR + h0]     = mm[rr][0];
                *(ull*)&mS[(SROWS * i + rr) * MSTR + h0 + 2] = mm[rr][1];
            }
        }

        __syncwarp();               // whole warp done reading slot s
        if (lane == 0) mbar_arrive(EMPTY(s));
        if (tid == 0 && i + NSLOT < ITERS) {
            mbar_wait(EMPTY(s), ph);               // both warps released slot s
            mbar_expect_tx(FULL(s), SROWS * Dd * 4);
            tma_bulk_1d(ringBase + s * (SROWS * Dd * 4),
                        growF + (i + NSLOT) * SROWS * Dd,
                        SROWS * Dd * 4, FULL(s));
        }
    }

    // s fully reduced across lanes; lanes 0,1 publish 4 heads each
    if (lane < 2) {
        *(ull*)&sS[h0]     = sA0;
        *(ull*)&sS[h0 + 2] = sA1;
    }
    __syncthreads();                // barrier #1: mS + sS complete

    // ---- epilogue: row = tid ----
    const int row = tid;
    float logit = __ldg(b2);
    #pragma unroll
    for (int hh = 0; hh < 16; hh++) {
        const float pre = 64.f * mS[row * MSTR + hh] + __ldg(&b1[hh]) - sS[hh];
        logit += fmaxf(pre, 0.f) * __ldg(&W2[hh]);
    }

    float mx = logit;
    #pragma unroll
    for (int o = 16; o >= 1; o >>= 1)
        mx = fmaxf(mx, __shfl_xor_sync(0xffffffffu, mx, o));
    if (lane == 0) red[0][p] = mx;
    __syncthreads();                // barrier #2
    const float mxAll = fmaxf(red[0][0], red[0][1]);

    const float e = __expf(logit - mxAll);
    float sm = e;
    #pragma unroll
    for (int o = 16; o >= 1; o >>= 1)
        sm += __shfl_xor_sync(0xffffffffu, sm, o);
    if (lane == 0) red[1][p] = sm;
    __syncthreads();                // barrier #3
    const float inv = 1.0f / (red[1][0] + red[1][1]);

    out[(size_t)b * Nn + row] = e * inv;
}

extern "C" void kernel_launch(void* const* d_in, const int* in_sizes, int n_in,
                              void* d_out, int out_size)
{
    attn_kernel<<<Bb, THREADS>>>(
        (const float*)d_in[0],   // members_embeds [2048,64,256]
        (const float*)d_in[1],   // item_embeds    [2048,256]
        (const float*)d_in[2],   // W1 [256,16]
        (const float*)d_in[3],   // b1 [16]
        (const float*)d_in[4],   // W2 [16,1]
        (const float*)d_in[5],   // b2 [1]
        (float*)d_out);          // out [2048,64]
}